// round 4
// baseline (speedup 1.0000x reference)
#include <cuda_runtime.h>
#include <math.h>

// x[16,64,256,256] f32, w[1,2,3,3] f32
#define B_   16
#define C_   64
#define H_   256
#define W_   256
#define TH   8
#define TW   32
#define HH_  (TH + 2)          // 10
#define HW_  (TW + 2)          // 34
#define NHALO (HH_ * HW_)      // 340
#define NINT  (TH * TW)        // 256
#define NT    512
#define HWIMG (H_ * W_)
#define CHW   (C_ * HWIMG)
#define CHALF 32               // channels per phase-1 half
#define NWORK (NHALO * 2)      // 680 phase-1 work items

// SMEM layout (floats):
//   s_x  [64*256] = 16384   (64 KB)
//   s_ps [680]  partial sums; low 340 reused as final avg
//   s_pm [680]  partial maxes; low 340 reused as final max
//   s_attn [256]
//   s_w  [18]
#define OFF_PS   (C_ * NINT)            // 16384
#define OFF_PM   (OFF_PS + NWORK)       // 17064
#define OFF_ATTN (OFF_PM + NWORK)       // 17744  (17744%4==0 -> 16B aligned)
#define OFF_W    (OFF_ATTN + NINT)      // 18000
#define SMEM_FLOATS (OFF_W + 20)        // 18020
#define SMEM_BYTES  (SMEM_FLOATS * 4)   // 72080 B -> 3 blocks/SM

__global__ void __launch_bounds__(NT, 3)
spatial_attention_kernel(const float* __restrict__ x,
                         const float* __restrict__ w,
                         float* __restrict__ out) {
    extern __shared__ float smem[];
    float* __restrict__ s_x    = smem;
    float* __restrict__ s_ps   = smem + OFF_PS;
    float* __restrict__ s_pm   = smem + OFF_PM;
    float* __restrict__ s_attn = smem + OFF_ATTN;
    float* __restrict__ s_w    = smem + OFF_W;

    const int tid = threadIdx.x;
    const int b   = blockIdx.z;
    const int y0  = blockIdx.y * TH;
    const int x0  = blockIdx.x * TW;
    const float* __restrict__ xb = x + (size_t)b * CHW;

    if (tid < 18) s_w[tid] = w[tid];

    // ---- Phase 1: stream tile once (2 channel-halves per halo pixel) ----
#pragma unroll
    for (int t = tid; t < NWORK; t += NT) {
        const int half = (t >= NHALO);
        const int pix  = t - half * NHALO;
        const int iy = pix / HW_;
        const int ix = pix - iy * HW_;
        const int Y  = y0 - 1 + iy;
        const int X  = x0 - 1 + ix;
        const bool inb = (Y >= 0) & (Y < H_) & (X >= 0) & (X < W_);
        const bool interior = (iy >= 1) & (iy < HH_ - 1) & (ix >= 1) & (ix < HW_ - 1);
        const int  ipix = (iy - 1) * TW + (ix - 1);

        float sum = 0.0f, mx = -1e30f;
        if (inb) {
            const float* __restrict__ p =
                xb + (size_t)(half * CHALF) * HWIMG + (size_t)Y * W_ + X;
            float* __restrict__ sx = s_x + (half * CHALF) * NINT + ipix;
#pragma unroll 16
            for (int c = 0; c < CHALF; c++) {
                float v = __ldg(p + (size_t)c * HWIMG);
                sum += v;
                mx = fmaxf(mx, v);
                if (interior) sx[c * NINT] = v;
            }
        }
        s_ps[t] = sum;
        s_pm[t] = mx;
    }
    __syncthreads();

    // ---- Combine halves -> final pooled maps (reuse low 340 slots) ------
    if (tid < NHALO) {
        const int iy = tid / HW_;
        const int ix = tid - iy * HW_;
        const int Y  = y0 - 1 + iy;
        const int X  = x0 - 1 + ix;
        const bool inb = (Y >= 0) & (Y < H_) & (X >= 0) & (X < W_);
        const float sum = s_ps[tid] + s_ps[tid + NHALO];
        const float mx  = fmaxf(s_pm[tid], s_pm[tid + NHALO]);
        s_ps[tid] = inb ? sum * (1.0f / C_) : 0.0f;   // avg (zero-pad for conv)
        s_pm[tid] = inb ? mx : 0.0f;                  // max
    }
    __syncthreads();

    // ---- Phase 2: 3x3 conv (concat [max, avg]) + sigmoid ----------------
    if (tid < NINT) {
        const int y  = tid >> 5;
        const int xq = tid & 31;
        float acc = 0.0f;
#pragma unroll
        for (int dy = 0; dy < 3; dy++) {
#pragma unroll
            for (int dx = 0; dx < 3; dx++) {
                const int hi = (y + dy) * HW_ + (xq + dx);
                acc += s_w[dy * 3 + dx]     * s_pm[hi];   // w ch0 -> max
                acc += s_w[9 + dy * 3 + dx] * s_ps[hi];   // w ch1 -> avg
            }
        }
        s_attn[tid] = 1.0f / (1.0f + expf(-acc));
    }
    __syncthreads();

    // ---- Phase 3: multiply from SMEM, float4 stores ---------------------
    // 256 px * 64 ch / 4 = 4096 float4; 8 per thread.
    const int g  = tid & 63;             // float4 group in tile (0..63)
    const int c0 = tid >> 6;             // 0..7
    const int py = g >> 3;               // row 0..7
    const int px = (g & 7) * 4;          // col 0,4,..,28
    const float4 a = *reinterpret_cast<const float4*>(&s_attn[py * TW + px]);
    const size_t obase = (size_t)b * CHW + (size_t)(y0 + py) * W_ + (x0 + px);

#pragma unroll
    for (int cc = 0; cc < C_; cc += 8) {
        const int c = cc + c0;
        float4 v = *reinterpret_cast<const float4*>(&s_x[c * NINT + g * 4]);
        v.x *= a.x; v.y *= a.y; v.z *= a.z; v.w *= a.w;
        __stcs(reinterpret_cast<float4*>(out + obase + (size_t)c * HWIMG), v);
    }
}

extern "C" void kernel_launch(void* const* d_in, const int* in_sizes, int n_in,
                              void* d_out, int out_size) {
    const float* x = (const float*)d_in[0];
    const float* w = (const float*)d_in[1];
    float* out     = (float*)d_out;

    cudaFuncSetAttribute(spatial_attention_kernel,
                         cudaFuncAttributeMaxDynamicSharedMemorySize, SMEM_BYTES);

    dim3 grid(W_ / TW, H_ / TH, B_);   // (8, 32, 16) = 4096 blocks
    spatial_attention_kernel<<<grid, NT, SMEM_BYTES>>>(x, w, out);
}

// round 5
// speedup vs baseline: 1.5151x; 1.5151x over previous
#include <cuda_runtime.h>
#include <math.h>

// x[16,64,256,256] f32, w[1,2,3,3] f32
#define B_   16
#define C_   64
#define H_   256
#define W_   256
#define TH   8
#define TW   32
#define HH_  (TH + 2)          // 10
#define HW_  (TW + 2)          // 34
#define NHALO (HH_ * HW_)      // 340
#define NINT  (TH * TW)        // 256
#define NT    256
#define KPP   2                // ceil(340/256)
#define HWIMG (H_ * W_)
#define CHW   (C_ * HWIMG)

__global__ void __launch_bounds__(NT, 8)
spatial_attention_kernel(const float* __restrict__ x,
                         const float* __restrict__ w,
                         float* __restrict__ out) {
    __shared__ float s_max[NHALO];
    __shared__ float s_avg[NHALO];
    __shared__ float s_attn[NINT];
    __shared__ float s_w[18];

    const int tid = threadIdx.x;
    const int b   = blockIdx.z;
    const int y0  = blockIdx.y * TH;
    const int x0  = blockIdx.x * TW;
    const float* __restrict__ xb = x + (size_t)b * CHW;

    if (tid < 18) s_w[tid] = w[tid];

    // ---- Phase 1: channel mean+max over 10x34 halo; data lands in L2 ----
    int  off[KPP];
    bool val[KPP];
#pragma unroll
    for (int k = 0; k < KPP; k++) {
        const int idx = tid + k * NT;
        val[k] = false; off[k] = 0;
        if (idx < NHALO) {
            const int iy = idx / HW_;
            const int ix = idx - iy * HW_;
            const int Y = y0 - 1 + iy;
            const int X = x0 - 1 + ix;
            if (Y >= 0 && Y < H_ && X >= 0 && X < W_) {
                val[k] = true;
                off[k] = Y * W_ + X;
            }
        }
    }

    float asum[KPP], amax[KPP];
#pragma unroll
    for (int k = 0; k < KPP; k++) { asum[k] = 0.0f; amax[k] = -1e30f; }

#pragma unroll 8
    for (int c = 0; c < C_; c++) {
        const float* __restrict__ xc = xb + (size_t)c * HWIMG;
#pragma unroll
        for (int k = 0; k < KPP; k++) {
            if (val[k]) {
                float v = __ldg(xc + off[k]);   // default policy: stays in L2 for phase 3
                asum[k] += v;
                amax[k] = fmaxf(amax[k], v);
            }
        }
    }

#pragma unroll
    for (int k = 0; k < KPP; k++) {
        const int idx = tid + k * NT;
        if (idx < NHALO) {
            s_avg[idx] = val[k] ? asum[k] * (1.0f / C_) : 0.0f;  // zero-pad
            s_max[idx] = val[k] ? amax[k] : 0.0f;
        }
    }
    __syncthreads();

    // ---- Phase 2: 3x3 conv (concat [max, avg]) + sigmoid ----------------
    {
        const int y  = tid >> 5;
        const int xq = tid & 31;
        float acc = 0.0f;
#pragma unroll
        for (int dy = 0; dy < 3; dy++) {
#pragma unroll
            for (int dx = 0; dx < 3; dx++) {
                const int hi = (y + dy) * HW_ + (xq + dx);
                acc += s_w[dy * 3 + dx]     * s_max[hi];   // w ch0 -> max
                acc += s_w[9 + dy * 3 + dx] * s_avg[hi];   // w ch1 -> avg
            }
        }
        s_attn[tid] = 1.0f / (1.0f + expf(-acc));
    }
    __syncthreads();

    // ---- Phase 3: re-read tile (L2-hot), multiply, streamed stores ------
    // 8x32 tile = 64 float4-groups per channel; 256 threads cover 4 channels
    // per pass, 16 passes.
    const int g  = tid & 63;             // float4 group (0..63)
    const int c0 = tid >> 6;             // 0..3
    const int py = g >> 3;               // row 0..7
    const int px = (g & 7) * 4;          // col 0,4,..,28
    const float4 a = *reinterpret_cast<const float4*>(&s_attn[py * TW + px]);
    const size_t base = (size_t)(y0 + py) * W_ + (x0 + px);
    float* __restrict__ ob = out + (size_t)b * CHW;

#pragma unroll
    for (int cc = 0; cc < C_; cc += 4) {
        const int c = cc + c0;
        float4 v = __ldcs(reinterpret_cast<const float4*>(xb + (size_t)c * HWIMG + base));
        v.x *= a.x; v.y *= a.y; v.z *= a.z; v.w *= a.w;
        __stcs(reinterpret_cast<float4*>(ob + (size_t)c * HWIMG + base), v);
    }
}

extern "C" void kernel_launch(void* const* d_in, const int* in_sizes, int n_in,
                              void* d_out, int out_size) {
    const float* x = (const float*)d_in[0];
    const float* w = (const float*)d_in[1];
    float* out     = (float*)d_out;

    dim3 grid(W_ / TW, H_ / TH, B_);   // (8, 32, 16) = 4096 blocks
    spatial_attention_kernel<<<grid, NT>>>(x, w, out);
}

// round 6
// speedup vs baseline: 1.6857x; 1.1126x over previous
#include <cuda_runtime.h>
#include <math.h>

// x[16,64,256,256] f32, w[1,2,3,3] f32
#define B_   16
#define C_   64
#define H_   256
#define W_   256
#define TH   8
#define TW   32
#define HH_  (TH + 2)          // 10
#define HW_  (TW + 2)          // 34
#define NHALO (HH_ * HW_)      // 340
#define NINT  (TH * TW)        // 256
#define NT    384
#define HWIMG (H_ * W_)
#define CHW   (C_ * HWIMG)

__global__ void __launch_bounds__(NT, 5)
spatial_attention_kernel(const float* __restrict__ x,
                         const float* __restrict__ w,
                         float* __restrict__ out) {
    __shared__ float s_max[NHALO];
    __shared__ float s_avg[NHALO];
    __shared__ float s_attn[NINT];
    __shared__ float s_w[18];

    const int tid = threadIdx.x;
    const int b   = blockIdx.z;
    const int y0  = blockIdx.y * TH;
    const int x0  = blockIdx.x * TW;
    const float* __restrict__ xb = x + (size_t)b * CHW;

    if (tid < 18) s_w[tid] = w[tid];

    // ---- Phase 1: one halo pixel per thread, all 64 channels ------------
    if (tid < NHALO) {
        const int iy = tid / HW_;
        const int ix = tid - iy * HW_;
        const int Y  = y0 - 1 + iy;
        const int X  = x0 - 1 + ix;
        const bool inb = (Y >= 0) & (Y < H_) & (X >= 0) & (X < W_);

        float s0 = 0.0f, s1 = 0.0f, m0 = -1e30f, m1 = -1e30f;
        if (inb) {
            const float* __restrict__ p = xb + (size_t)Y * W_ + X;
#pragma unroll 8
            for (int c = 0; c < C_; c += 2) {
                const float v0 = __ldg(p + (size_t)c       * HWIMG);
                const float v1 = __ldg(p + (size_t)(c + 1) * HWIMG);
                s0 += v0; m0 = fmaxf(m0, v0);
                s1 += v1; m1 = fmaxf(m1, v1);
            }
        }
        s_avg[tid] = inb ? (s0 + s1) * (1.0f / C_) : 0.0f;  // zero-pad for conv
        s_max[tid] = inb ? fmaxf(m0, m1) : 0.0f;
    }
    __syncthreads();

    // ---- Phase 2: 3x3 conv (concat [max, avg]) + sigmoid ----------------
    if (tid < NINT) {
        const int y  = tid >> 5;
        const int xq = tid & 31;
        float acc = 0.0f;
#pragma unroll
        for (int dy = 0; dy < 3; dy++) {
#pragma unroll
            for (int dx = 0; dx < 3; dx++) {
                const int hi = (y + dy) * HW_ + (xq + dx);
                acc += s_w[dy * 3 + dx]     * s_max[hi];   // w ch0 -> max
                acc += s_w[9 + dy * 3 + dx] * s_avg[hi];   // w ch1 -> avg
            }
        }
        s_attn[tid] = 1.0f / (1.0f + expf(-acc));
    }
    __syncthreads();

    // ---- Phase 3: re-read tile (L2-hot), multiply, streamed stores ------
    // 256 px * 64 ch / 4 = 4096 float4. Thread owns fixed float4-group
    // (g = tid & 63) and channels c0, c0+6, c0+12, ...
    const int g  = tid & 63;             // float4 group in tile
    const int c0 = tid >> 6;             // 0..5
    const int py = g >> 3;               // row 0..7
    const int px = (g & 7) * 4;          // col 0,4,..,28
    const float4 a = *reinterpret_cast<const float4*>(&s_attn[py * TW + px]);
    const size_t base = (size_t)(y0 + py) * W_ + (x0 + px);
    float* __restrict__ ob = out + (size_t)b * CHW;

    for (int c = c0; c < C_; c += 6) {
        float4 v = __ldcs(reinterpret_cast<const float4*>(xb + (size_t)c * HWIMG + base));
        v.x *= a.x; v.y *= a.y; v.z *= a.z; v.w *= a.w;
        __stcs(reinterpret_cast<float4*>(ob + (size_t)c * HWIMG + base), v);
    }
}

extern "C" void kernel_launch(void* const* d_in, const int* in_sizes, int n_in,
                              void* d_out, int out_size) {
    const float* x = (const float*)d_in[0];
    const float* w = (const float*)d_in[1];
    float* out     = (float*)d_out;

    dim3 grid(W_ / TW, H_ / TH, B_);   // (8, 32, 16) = 4096 blocks
    spatial_attention_kernel<<<grid, NT>>>(x, w, out);
}